// round 12
// baseline (speedup 1.0000x reference)
#include <cuda_runtime.h>
#include <cuda_bf16.h>
#include <math.h>
#include <cstdint>

// Problem dims
#define Bv 128
#define Tv 1024
#define Iv 512
#define Hv 1024
#define Ov 256

#define NBLK_SCAN 128   // 8 k-chunks x 16 n-tiles
#define KCHUNKS   8

typedef unsigned long long ull;

// -------- scratch (device globals: no allocation allowed) --------
__device__ __nv_bfloat16 g_xh[(size_t)Tv * Bv * Iv]; // x split hi, [t][b][i]
__device__ __nv_bfloat16 g_xl[(size_t)Tv * Bv * Iv]; // x split lo, [t][b][i]
__device__ __nv_bfloat16 g_hh[Bv * Hv];              // hidden state, bf16 hi
__device__ __nv_bfloat16 g_hl[Bv * Hv];              // hidden state, bf16 lo
__device__ float g_part[KCHUNKS][Bv * Hv];           // split-K partials (4 MB)
__device__ unsigned g_bar_count;
__device__ volatile unsigned g_bar_gen;

// -------- mma.sync / ldmatrix helpers --------
__device__ __forceinline__ uint32_t smem_u32(const void* p) {
    uint32_t a;
    asm("{ .reg .u64 t; cvta.to.shared.u64 t, %1; cvt.u32.u64 %0, t; }"
        : "=r"(a) : "l"(p));
    return a;
}
__device__ __forceinline__ void ldsm4(uint32_t r[4], uint32_t addr) {
    asm volatile("ldmatrix.sync.aligned.m8n8.x4.shared.b16 {%0,%1,%2,%3}, [%4];"
                 : "=r"(r[0]), "=r"(r[1]), "=r"(r[2]), "=r"(r[3]) : "r"(addr));
}
__device__ __forceinline__ void mma_bf16(float d[4], const uint32_t a[4],
                                         const uint32_t b0, const uint32_t b1) {
    asm volatile(
        "mma.sync.aligned.m16n8k16.row.col.f32.bf16.bf16.f32 "
        "{%0,%1,%2,%3}, {%4,%5,%6,%7}, {%8,%9}, {%0,%1,%2,%3};"
        : "+f"(d[0]), "+f"(d[1]), "+f"(d[2]), "+f"(d[3])
        : "r"(a[0]), "r"(a[1]), "r"(a[2]), "r"(a[3]), "r"(b0), "r"(b1));
}
__device__ __forceinline__ uint32_t bf16pack(float a, float b) {
    __nv_bfloat16 x = __float2bfloat16(a);
    __nv_bfloat16 y = __float2bfloat16(b);
    return (uint32_t)__bfloat16_as_ushort(x) |
           ((uint32_t)__bfloat16_as_ushort(y) << 16);
}

// ============================================================
// Kernel 0: split x into bf16 hi/lo, transpose [b][t][i] -> [t][b][i]
// (R10-proven; DRAM-bound at ~80%)
// ============================================================
__global__ void __launch_bounds__(256) split_x(const float* __restrict__ X)
{
    size_t idx8 = (size_t)blockIdx.x * 256 + threadIdx.x;
    if (idx8 >= (size_t)Bv * Tv * Iv / 8) return;
    int i = (int)(idx8 & 63) * 8;
    int t = (int)((idx8 >> 6) & 1023);
    int b = (int)(idx8 >> 16);

    const float* src = X + (((size_t)b * Tv + t) * Iv + i);
    float4 f0 = *(const float4*)(src + 0);
    float4 f1 = *(const float4*)(src + 4);
    float f[8] = {f0.x, f0.y, f0.z, f0.w, f1.x, f1.y, f1.z, f1.w};

    uint32_t hi[4], lo[4];
#pragma unroll
    for (int j = 0; j < 4; j++) {
        __nv_bfloat16 h0 = __float2bfloat16(f[2 * j]);
        __nv_bfloat16 h1 = __float2bfloat16(f[2 * j + 1]);
        hi[j] = (uint32_t)__bfloat16_as_ushort(h0) |
                ((uint32_t)__bfloat16_as_ushort(h1) << 16);
        lo[j] = bf16pack(f[2 * j] - __bfloat162float(h0),
                         f[2 * j + 1] - __bfloat162float(h1));
    }
    size_t o = (((size_t)t * Bv + b) * Iv + i);
    *(uint4*)&g_xh[o] = *(const uint4*)hi;
    *(uint4*)&g_xl[o] = *(const uint4*)lo;
}

// ============================================================
// Kernel B: persistent fused scan, kc=8 x nt=16 decomposition.
// CTA (kc,nt): part[kc][:, nt*64..] = h @ Wr[kc*128 slice] + x[t] @ Wk[kc*64 slice]
// SMEM 144KB:
//   Ahh[2][128][128B] Ahl   (h slice K=128, two 128B-row subtiles)     64K
//   Bwh[2][64][128B]  Bwl   (Wr [n][k], two k-subtiles)                32K
//   Xhh[128][128B]    Xhl   (x slice K=64)                             32K
//   Kwh[64][128B]     Kwl   (Wk [n][k], K=64)                          16K
// Barrier: R10 flat atomic (best measured).
// ============================================================
__global__ void __launch_bounds__(256, 1) scan_kernel(
    const float* __restrict__ WR, const float* __restrict__ WK,
    const float* __restrict__ bias)
{
    extern __shared__ __align__(1024) char smem[];
    char* sAhh = smem;                     // 32768
    char* sAhl = smem + 32768;             // 32768
    char* sBwh = smem + 65536;             // 16384
    char* sBwl = smem + 81920;             // 16384
    char* sXhh = smem + 98304;             // 16384
    char* sXhl = smem + 114688;            // 16384
    char* sKwh = smem + 131072;            // 8192
    char* sKwl = smem + 139264;            // 8192
    const uint32_t pAhh = smem_u32(smem);
    const uint32_t pAhl = pAhh + 32768;
    const uint32_t pBwh = pAhh + 65536;
    const uint32_t pBwl = pAhh + 81920;
    const uint32_t pXhh = pAhh + 98304;
    const uint32_t pXhl = pAhh + 114688;
    const uint32_t pKwh = pAhh + 131072;
    const uint32_t pKwl = pAhh + 139264;

    const int tid = threadIdx.x;
    const int wid = tid >> 5;
    const int lid = tid & 31;
    const int bi = blockIdx.x;
    const int kc = bi >> 4;            // 0..7
    const int nt = bi & 15;            // 0..15
    const int kbase = kc * 128;        // Wr K slice
    const int xbase = kc * 64;         // Wk K slice
    const int nbase = nt * 64;
    const int e = (bi * 256 + tid) * 4;

    const int wm = wid & 1;            // M: 2 warps x 64
    const int wn = wid >> 1;           // N: 4 warps x 16

    // ldmatrix lane invariants (R7-proven mapping)
    const int rowA = ((lid >> 3) & 1) * 8 + (lid & 7);
    const int khA  = (lid >> 4) * 16;
    const int rowB = ((lid >> 4) & 1) * 8 + (lid & 7);
    const int khB  = ((lid >> 3) & 1) * 16;
    const int sw   = (lid & 7) << 4;
    const uint32_t aHiBase = pAhh + (wm * 64 + rowA) * 128;
    const uint32_t aLoBase = pAhl + (wm * 64 + rowA) * 128;
    const uint32_t bHiBase = pBwh + (wn * 16 + rowB) * 128;
    const uint32_t bLoBase = pBwl + (wn * 16 + rowB) * 128;
    const uint32_t xHiBase = pXhh + (wm * 64 + rowA) * 128;
    const uint32_t xLoBase = pXhl + (wm * 64 + rowA) * 128;
    const uint32_t kHiBase = pKwh + (wn * 16 + rowB) * 128;
    const uint32_t kLoBase = pKwl + (wn * 16 + rowB) * 128;

    // ---- preload Wr slice: [n 0..63][k 0..127], two k-subtiles, swizzled ----
    for (int idx = tid; idx < 64 * 128; idx += 256) {
        int n = idx & 63;
        int k = idx >> 6;
        float w = WR[(size_t)(kbase + k) * Hv + nbase + n];
        __nv_bfloat16 wh = __float2bfloat16(w);
        __nv_bfloat16 wl = __float2bfloat16(w - __bfloat162float(wh));
        uint32_t off = (uint32_t)(k >> 6) * 8192 + n * 128 +
                       (((k & 63) * 2) ^ ((n & 7) << 4));
        *(__nv_bfloat16*)(sBwh + off) = wh;
        *(__nv_bfloat16*)(sBwl + off) = wl;
    }
    // ---- preload Wk slice: [n 0..63][k 0..63], swizzled ----
    for (int idx = tid; idx < 64 * 64; idx += 256) {
        int n = idx & 63;
        int k = idx >> 6;
        float w = WK[(size_t)(xbase + k) * Hv + nbase + n];
        __nv_bfloat16 wh = __float2bfloat16(w);
        __nv_bfloat16 wl = __float2bfloat16(w - __bfloat162float(wh));
        uint32_t off = n * 128 + ((k * 2) ^ ((n & 7) << 4));
        *(__nv_bfloat16*)(sKwh + off) = wh;
        *(__nv_bfloat16*)(sKwl + off) = wl;
    }

    *(ull*)&g_hh[e] = 0ull;
    *(ull*)&g_hl[e] = 0ull;

    float4 bb = *(const float4*)&bias[tid * 4];

    const int srow = tid >> 1;
    const int shalf = tid & 1;
    const uint32_t rb = srow * 128;
    const uint32_t sws = (srow & 7) << 4;
    const uint32_t soff = shalf * 64;

    // ---- stage x[0] tile (K=64: 64B half per thread, hi+lo) ----
    {
        const char* xh = (const char*)(g_xh + (size_t)srow * Iv + xbase) + soff;
        const char* xl = (const char*)(g_xl + (size_t)srow * Iv + xbase) + soff;
#pragma unroll
        for (int j = 0; j < 4; j++) {
            uint4 a = __ldcg((const uint4*)xh + j);
            uint4 b = __ldcg((const uint4*)xl + j);
            *(uint4*)(sXhh + rb + ((soff + j * 16) ^ sws)) = a;
            *(uint4*)(sXhl + rb + ((soff + j * 16) ^ sws)) = b;
        }
    }

    // ---- initial barrier (R10 flat) ----
    __threadfence();
    __syncthreads();
    if (tid == 0) {
        unsigned gen = g_bar_gen;
        unsigned prev = atomicAdd(&g_bar_count, 1u);
        if (prev == NBLK_SCAN - 1) { g_bar_count = 0; __threadfence(); g_bar_gen = gen + 1; }
        else { while (g_bar_gen == gen) {} }
    }
    __syncthreads();

#pragma unroll 1
    for (int t = 0; t < Tv; t++) {
        // ---- stage h slice (K=128: two 64B halves per thread, hi+lo) ----
        {
#pragma unroll
            for (int s = 0; s < 2; s++) {
                const char* sh = (const char*)(g_hh + (size_t)srow * Hv + kbase + s * 64) + soff;
                const char* sl = (const char*)(g_hl + (size_t)srow * Hv + kbase + s * 64) + soff;
                uint4 h0 = __ldcg((const uint4*)sh + 0);
                uint4 h1 = __ldcg((const uint4*)sh + 1);
                uint4 h2 = __ldcg((const uint4*)sh + 2);
                uint4 h3 = __ldcg((const uint4*)sh + 3);
                uint4 l0 = __ldcg((const uint4*)sl + 0);
                uint4 l1 = __ldcg((const uint4*)sl + 1);
                uint4 l2 = __ldcg((const uint4*)sl + 2);
                uint4 l3 = __ldcg((const uint4*)sl + 3);
                uint32_t sb = (uint32_t)s * 16384 + rb;
                *(uint4*)(sAhh + sb + ((soff +  0) ^ sws)) = h0;
                *(uint4*)(sAhh + sb + ((soff + 16) ^ sws)) = h1;
                *(uint4*)(sAhh + sb + ((soff + 32) ^ sws)) = h2;
                *(uint4*)(sAhh + sb + ((soff + 48) ^ sws)) = h3;
                *(uint4*)(sAhl + sb + ((soff +  0) ^ sws)) = l0;
                *(uint4*)(sAhl + sb + ((soff + 16) ^ sws)) = l1;
                *(uint4*)(sAhl + sb + ((soff + 32) ^ sws)) = l2;
                *(uint4*)(sAhl + sb + ((soff + 48) ^ sws)) = l3;
            }
        }
        __syncthreads();

        // ---- GEMM: rec (K=128) + xp (K=64), 3-term each ----
        float D[4][2][4];
#pragma unroll
        for (int i = 0; i < 4; i++)
#pragma unroll
            for (int j = 0; j < 2; j++)
#pragma unroll
                for (int q = 0; q < 4; q++) D[i][j][q] = 0.f;

#pragma unroll
        for (int ks = 0; ks < 8; ks++) {
            const uint32_t sub = (uint32_t)(ks >> 2);
            const uint32_t koffA = (((ks & 3) * 32) | khA) ^ sw;
            const uint32_t koffB = (((ks & 3) * 32) | khB) ^ sw;
            const uint32_t aOff = sub * 16384 + koffA;
            const uint32_t bOff = sub * 8192 + koffB;
            uint32_t Ah[4][4], Al[4][4], Bh[4], Bl[4];
#pragma unroll
            for (int mt = 0; mt < 4; mt++) {
                ldsm4(Ah[mt], aHiBase + mt * 2048 + aOff);
                ldsm4(Al[mt], aLoBase + mt * 2048 + aOff);
            }
            ldsm4(Bh, bHiBase + bOff);
            ldsm4(Bl, bLoBase + bOff);
#pragma unroll
            for (int mt = 0; mt < 4; mt++) {
#pragma unroll
                for (int ntl = 0; ntl < 2; ntl++) {
                    const int q = ntl * 2;
                    mma_bf16(D[mt][ntl], Ah[mt], Bh[q], Bh[q + 1]);
                    mma_bf16(D[mt][ntl], Al[mt], Bh[q], Bh[q + 1]);
                    mma_bf16(D[mt][ntl], Ah[mt], Bl[q], Bl[q + 1]);
                }
            }
        }
#pragma unroll
        for (int ks = 0; ks < 4; ks++) {
            const uint32_t koffA = ((ks * 32) | khA) ^ sw;
            const uint32_t koffB = ((ks * 32) | khB) ^ sw;
            uint32_t Ah[4][4], Al[4][4], Bh[4], Bl[4];
#pragma unroll
            for (int mt = 0; mt < 4; mt++) {
                ldsm4(Ah[mt], xHiBase + mt * 2048 + koffA);
                ldsm4(Al[mt], xLoBase + mt * 2048 + koffA);
            }
            ldsm4(Bh, kHiBase + koffB);
            ldsm4(Bl, kLoBase + koffB);
#pragma unroll
            for (int mt = 0; mt < 4; mt++) {
#pragma unroll
                for (int ntl = 0; ntl < 2; ntl++) {
                    const int q = ntl * 2;
                    mma_bf16(D[mt][ntl], Ah[mt], Bh[q], Bh[q + 1]);
                    mma_bf16(D[mt][ntl], Al[mt], Bh[q], Bh[q + 1]);
                    mma_bf16(D[mt][ntl], Ah[mt], Bl[q], Bl[q + 1]);
                }
            }
        }

        // ---- write split-K partials ----
        {
            const int g = lid >> 2, c2 = (lid & 3) * 2;
            float* P = g_part[kc];
#pragma unroll
            for (int mt = 0; mt < 4; mt++) {
#pragma unroll
                for (int ntl = 0; ntl < 2; ntl++) {
                    int row0 = wm * 64 + mt * 16 + g;
                    int col = nbase + wn * 16 + ntl * 8 + c2;
                    float2 v0 = {D[mt][ntl][0], D[mt][ntl][1]};
                    float2 v1 = {D[mt][ntl][2], D[mt][ntl][3]};
                    *(float2*)&P[(size_t)row0 * Hv + col] = v0;
                    *(float2*)&P[(size_t)(row0 + 8) * Hv + col] = v1;
                }
            }
        }

        // ---- barrier 1, x[t+1] staging in its shadow (R10 form) ----
        __threadfence();
        __syncthreads();
        if (t + 1 < Tv) {
            const char* xh = (const char*)(g_xh + ((size_t)(t + 1) * Bv + srow) * Iv + xbase) + soff;
            const char* xl = (const char*)(g_xl + ((size_t)(t + 1) * Bv + srow) * Iv + xbase) + soff;
#pragma unroll
            for (int j = 0; j < 4; j++) {
                uint4 a = __ldcg((const uint4*)xh + j);
                uint4 b = __ldcg((const uint4*)xl + j);
                *(uint4*)(sXhh + rb + ((soff + j * 16) ^ sws)) = a;
                *(uint4*)(sXhl + rb + ((soff + j * 16) ^ sws)) = b;
            }
        }
        if (tid == 0) {
            unsigned gen = g_bar_gen;
            unsigned prev = atomicAdd(&g_bar_count, 1u);
            if (prev == NBLK_SCAN - 1) { g_bar_count = 0; __threadfence(); g_bar_gen = gen + 1; }
            else { while (g_bar_gen == gen) {} }
        }
        __syncthreads();

        // ---- phase 2: reduce 8 partials + bias + tanh -> h (bf16 hi/lo) ----
        {
            float4 s = bb;
#pragma unroll
            for (int c = 0; c < KCHUNKS; c++) {
                float4 p = __ldcg((const float4*)&g_part[c][e]);
                s.x += p.x; s.y += p.y; s.z += p.z; s.w += p.w;
            }
            float h[4] = {tanhf(s.x), tanhf(s.y), tanhf(s.z), tanhf(s.w)};
            unsigned short hh[4], hl[4];
#pragma unroll
            for (int j = 0; j < 4; j++) {
                __nv_bfloat16 a = __float2bfloat16(h[j]);
                __nv_bfloat16 b = __float2bfloat16(h[j] - __bfloat162float(a));
                hh[j] = __bfloat16_as_ushort(a);
                hl[j] = __bfloat16_as_ushort(b);
            }
            *(ull*)&g_hh[e] = *(const ull*)hh;
            *(ull*)&g_hl[e] = *(const ull*)hl;
        }

        // ---- barrier 2 ----
        __threadfence();
        __syncthreads();
        if (tid == 0) {
            unsigned gen = g_bar_gen;
            unsigned prev = atomicAdd(&g_bar_count, 1u);
            if (prev == NBLK_SCAN - 1) { g_bar_count = 0; __threadfence(); g_bar_gen = gen + 1; }
            else { while (g_bar_gen == gen) {} }
        }
        __syncthreads();
    }
}

// ============================================================
// Kernel C: out[b][o] = h_last[b][:] @ fc_w[:, o] + fc_b[o]
// ============================================================
__global__ void __launch_bounds__(256, 1) fc_kernel(
    const float* __restrict__ fcw, const float* __restrict__ fcb,
    float* __restrict__ out)
{
    __shared__ float hs[Hv];
    const int b = blockIdx.x;
    for (int i = threadIdx.x; i < Hv; i += 256) {
        hs[i] = __bfloat162float(g_hh[(size_t)b * Hv + i]) +
                __bfloat162float(g_hl[(size_t)b * Hv + i]);
    }
    __syncthreads();

    const int o = threadIdx.x;
    float a0 = 0.f, a1 = 0.f, a2 = 0.f, a3 = 0.f;
#pragma unroll 4
    for (int k = 0; k < Hv; k += 4) {
        a0 = fmaf(hs[k + 0], fcw[(size_t)(k + 0) * Ov + o], a0);
        a1 = fmaf(hs[k + 1], fcw[(size_t)(k + 1) * Ov + o], a1);
        a2 = fmaf(hs[k + 2], fcw[(size_t)(k + 2) * Ov + o], a2);
        a3 = fmaf(hs[k + 3], fcw[(size_t)(k + 3) * Ov + o], a3);
    }
    out[(size_t)b * Ov + o] = (a0 + a1) + (a2 + a3) + fcb[o];
}

// ============================================================
extern "C" void kernel_launch(void* const* d_in, const int* in_sizes, int n_in,
                              void* d_out, int out_size)
{
    const float* x   = (const float*)d_in[0];
    const float* wk  = (const float*)d_in[1];
    const float* wr  = (const float*)d_in[2];
    const float* bs  = (const float*)d_in[3];
    const float* fcw = (const float*)d_in[4];
    const float* fcb = (const float*)d_in[5];
    float* out = (float*)d_out;

    static int smem_set = 0;
    if (!smem_set) {
        cudaFuncSetAttribute(scan_kernel,
                             cudaFuncAttributeMaxDynamicSharedMemorySize, 147456);
        smem_set = 1;
    }

    size_t nx8 = (size_t)Bv * Tv * Iv / 8;
    split_x<<<(unsigned)((nx8 + 255) / 256), 256>>>(x);
    scan_kernel<<<NBLK_SCAN, 256, 147456>>>(wr, wk, bs);
    fc_kernel<<<Bv, 256>>>(fcw, fcb, out);
}